// round 2
// baseline (speedup 1.0000x reference)
#include <cuda_runtime.h>
#include <cstdint>

#define NN 50000
#define DD 256
#define EE 320000
#define TOT (NN * DD)

// ---------------- scratch (static __device__ — no allocation allowed) ----------------
__device__ int g_cnt_a[NN], g_cnt_b[NN], g_cur_a[NN], g_cur_b[NN];
__device__ int g_off_a[NN + 1], g_off_b[NN + 1];
__device__ int g_csr_a[EE], g_csr_b[EE];
__device__ float g_mt[NN * DD], g_ms[NN * DD];
__device__ float g_xs0[NN * DD], g_xt0[NN * DD], g_xs1[NN * DD], g_xt1[NN * DD];

// ---------------- threefry-2x32 (exactly JAX's) ----------------
__host__ __device__ __forceinline__ unsigned rotl32(unsigned x, int d) {
    return (x << d) | (x >> (32 - d));
}

__host__ __device__ __forceinline__ void tf2x32(unsigned k0, unsigned k1,
                                                unsigned x0, unsigned x1,
                                                unsigned& o0, unsigned& o1) {
    unsigned ks2 = k0 ^ k1 ^ 0x1BD11BDAu;
    x0 += k0; x1 += k1;
#define TF_ROUND(r) { x0 += x1; x1 = rotl32(x1, r); x1 ^= x0; }
    TF_ROUND(13) TF_ROUND(15) TF_ROUND(26) TF_ROUND(6)
    x0 += k1;  x1 += ks2 + 1u;
    TF_ROUND(17) TF_ROUND(29) TF_ROUND(16) TF_ROUND(24)
    x0 += ks2; x1 += k0 + 2u;
    TF_ROUND(13) TF_ROUND(15) TF_ROUND(26) TF_ROUND(6)
    x0 += k0;  x1 += k1 + 3u;
    TF_ROUND(17) TF_ROUND(29) TF_ROUND(16) TF_ROUND(24)
    x0 += k1;  x1 += ks2 + 4u;
    TF_ROUND(13) TF_ROUND(15) TF_ROUND(26) TF_ROUND(6)
    x0 += ks2; x1 += k0 + 5u;
#undef TF_ROUND
    o0 = x0; o1 = x1;
}

// partitionable-threefry 32-bit random bits for flat index i (hi counter = 0)
__device__ __forceinline__ unsigned jax_bits32(unsigned k0, unsigned k1, unsigned i) {
    unsigned o0, o1;
    tf2x32(k0, k1, 0u, i, o0, o1);
    return o0 ^ o1;
}

// ---------------- CSR build ----------------
__global__ void zero_kernel() {
    int i = blockIdx.x * blockDim.x + threadIdx.x;
    if (i < NN) { g_cnt_a[i] = 0; g_cnt_b[i] = 0; g_cur_a[i] = 0; g_cur_b[i] = 0; }
}

__global__ void count_kernel(const int* __restrict__ dst_a, const int* __restrict__ dst_b) {
    int e = blockIdx.x * blockDim.x + threadIdx.x;
    if (e < EE) {
        atomicAdd(&g_cnt_a[dst_a[e]], 1);
        atomicAdd(&g_cnt_b[dst_b[e]], 1);
    }
}

__global__ void scan_kernel(const int* __restrict__ cnt, int* __restrict__ off) {
    __shared__ int buf[2][1024];
    int t = threadIdx.x;
    const int per = (NN + 1023) >> 10;  // 49
    int base = t * per;
    int s = 0;
    for (int i = 0; i < per; i++) { int idx = base + i; if (idx < NN) s += cnt[idx]; }
    buf[0][t] = s;
    __syncthreads();
    int cur = 0;
    for (int d = 1; d < 1024; d <<= 1) {
        int v = buf[cur][t];
        if (t >= d) v += buf[cur][t - d];
        buf[cur ^ 1][t] = v;
        __syncthreads();
        cur ^= 1;
    }
    int run = buf[cur][t] - s;  // exclusive prefix
    for (int i = 0; i < per; i++) {
        int idx = base + i;
        if (idx < NN) { off[idx] = run; run += cnt[idx]; }
    }
    if (t == 1023) off[NN] = run;
}

__global__ void fill_kernel(const int* __restrict__ src_a, const int* __restrict__ dst_a,
                            const int* __restrict__ src_b, const int* __restrict__ dst_b) {
    int e = blockIdx.x * blockDim.x + threadIdx.x;
    if (e < EE) {
        int da = dst_a[e];
        int pa = g_off_a[da] + atomicAdd(&g_cur_a[da], 1);
        g_csr_a[pa] = src_a[e];
        int db = dst_b[e];
        int pb = g_off_b[db] + atomicAdd(&g_cur_b[db], 1);
        g_csr_b[pb] = src_b[e];
    }
}

// ---------------- segment mean (one block per destination, 64 threads * float4 = 256) ----------------
__global__ void segmean_kernel(const float* __restrict__ x, const int* __restrict__ off,
                               const int* __restrict__ csr, float* __restrict__ out) {
    int r = blockIdx.x;
    int t = threadIdx.x;  // 0..63
    int s0 = off[r], s1 = off[r + 1];
    float4 acc = make_float4(0.f, 0.f, 0.f, 0.f);
    for (int e = s0; e < s1; e++) {
        int src = csr[e];
        float4 v = __ldg((const float4*)(x + (size_t)src * DD) + t);
        acc.x += v.x; acc.y += v.y; acc.z += v.z; acc.w += v.w;
    }
    int cnt = s1 - s0;
    float inv = 1.0f / (float)(cnt > 0 ? cnt : 1);
    acc.x *= inv; acc.y *= inv; acc.z *= inv; acc.w *= inv;
    ((float4*)(out + (size_t)r * DD))[t] = acc;
}

// ---------------- fused dual-GEMM: C = A1@W1 + A2@W2 + bias, then leaky-relu ----------------
__global__ __launch_bounds__(256, 2) void gemm_fused(
    const float* __restrict__ A1, const float* __restrict__ A2,
    const float* __restrict__ W1, const float* __restrict__ W2,
    const float* __restrict__ bias, float* __restrict__ C, int M) {
    __shared__ float As[16][128];
    __shared__ float Bs[16][128];
    const int tid = threadIdx.x;
    const int tx = tid & 15, ty = tid >> 4;
    const int bx = blockIdx.x, by = blockIdx.y;
    const int rowBase = by * 128;
    float acc[8][8];
#pragma unroll
    for (int i = 0; i < 8; i++)
#pragma unroll
        for (int j = 0; j < 8; j++) acc[i][j] = 0.f;

    const int j0 = tid * 2, j1 = tid * 2 + 1;
    const int ar0 = j0 >> 2, ac0 = (j0 & 3) * 4;
    const int ar1 = j1 >> 2, ac1 = (j1 & 3) * 4;
    const int br0 = j0 >> 5, bc0 = (j0 & 31) * 4;
    const int br1 = j1 >> 5, bc1 = (j1 & 31) * 4;

    for (int phase = 0; phase < 2; ++phase) {
        const float* A = phase ? A2 : A1;
        const float* W = phase ? W2 : W1;
        for (int k0 = 0; k0 < 256; k0 += 16) {
            float4 va0 = make_float4(0.f, 0.f, 0.f, 0.f), va1 = va0;
            int gr0 = rowBase + ar0, gr1 = rowBase + ar1;
            if (gr0 < M) va0 = *(const float4*)(A + (size_t)gr0 * 256 + k0 + ac0);
            if (gr1 < M) va1 = *(const float4*)(A + (size_t)gr1 * 256 + k0 + ac1);
            float4 vb0 = *(const float4*)(W + (size_t)(k0 + br0) * 256 + bx * 128 + bc0);
            float4 vb1 = *(const float4*)(W + (size_t)(k0 + br1) * 256 + bx * 128 + bc1);
            __syncthreads();  // previous tile fully consumed
            As[ac0 + 0][ar0] = va0.x; As[ac0 + 1][ar0] = va0.y;
            As[ac0 + 2][ar0] = va0.z; As[ac0 + 3][ar0] = va0.w;
            As[ac1 + 0][ar1] = va1.x; As[ac1 + 1][ar1] = va1.y;
            As[ac1 + 2][ar1] = va1.z; As[ac1 + 3][ar1] = va1.w;
            *(float4*)&Bs[br0][bc0] = vb0;
            *(float4*)&Bs[br1][bc1] = vb1;
            __syncthreads();
#pragma unroll
            for (int k = 0; k < 16; k++) {
                float4 a0 = *(const float4*)&As[k][ty * 4];
                float4 a1 = *(const float4*)&As[k][64 + ty * 4];
                float4 b0 = *(const float4*)&Bs[k][tx * 4];
                float4 b1 = *(const float4*)&Bs[k][64 + tx * 4];
                float a[8] = {a0.x, a0.y, a0.z, a0.w, a1.x, a1.y, a1.z, a1.w};
                float b[8] = {b0.x, b0.y, b0.z, b0.w, b1.x, b1.y, b1.z, b1.w};
#pragma unroll
                for (int i = 0; i < 8; i++)
#pragma unroll
                    for (int j = 0; j < 8; j++) acc[i][j] += a[i] * b[j];
            }
        }
    }

#pragma unroll
    for (int ih = 0; ih < 2; ih++)
#pragma unroll
        for (int i = 0; i < 4; i++) {
            int r = rowBase + ih * 64 + ty * 4 + i;
            if (r >= M) continue;
#pragma unroll
            for (int jh = 0; jh < 2; jh++) {
                int cb = bx * 128 + jh * 64 + tx * 4;
                float4 bv = *(const float4*)(bias + cb);
                float4 v;
                v.x = acc[ih * 4 + i][jh * 4 + 0] + bv.x;
                v.y = acc[ih * 4 + i][jh * 4 + 1] + bv.y;
                v.z = acc[ih * 4 + i][jh * 4 + 2] + bv.z;
                v.w = acc[ih * 4 + i][jh * 4 + 3] + bv.w;
                v.x = v.x >= 0.f ? v.x : 0.01f * v.x;
                v.y = v.y >= 0.f ? v.y : 0.01f * v.y;
                v.z = v.z >= 0.f ? v.z : 0.01f * v.z;
                v.w = v.w >= 0.f ? v.w : 0.01f * v.w;
                *(float4*)(C + (size_t)r * 256 + cb) = v;
            }
        }
}

// ---------------- dropout: JAX partitionable threefry, bit-exact ----------------
// bits[i] = o0 ^ o1 with (o0,o1) = threefry2x32(key, hi=0, lo=i)
// u = bitcast((bits>>9)|0x3f800000) - 1 ;  keep = u < 0.9 ; scale 1/0.9
__global__ __launch_bounds__(256) void dropout_kernel(float* __restrict__ x,
                                                      unsigned k0, unsigned k1) {
    int base = (blockIdx.x * blockDim.x + threadIdx.x) * 4;
    if (base >= TOT) return;
    float4 v = *(float4*)(x + base);
    const float sc = 1.0f / 0.9f;
    unsigned b0 = jax_bits32(k0, k1, (unsigned)(base + 0));
    unsigned b1 = jax_bits32(k0, k1, (unsigned)(base + 1));
    unsigned b2 = jax_bits32(k0, k1, (unsigned)(base + 2));
    unsigned b3 = jax_bits32(k0, k1, (unsigned)(base + 3));
    float u0 = __uint_as_float((b0 >> 9) | 0x3f800000u) - 1.0f;
    float u1 = __uint_as_float((b1 >> 9) | 0x3f800000u) - 1.0f;
    float u2 = __uint_as_float((b2 >> 9) | 0x3f800000u) - 1.0f;
    float u3 = __uint_as_float((b3 >> 9) | 0x3f800000u) - 1.0f;
    v.x = (u0 < 0.9f) ? v.x * sc : 0.0f;
    v.y = (u1 < 0.9f) ? v.y * sc : 0.0f;
    v.z = (u2 < 0.9f) ? v.z * sc : 0.0f;
    v.w = (u3 < 0.9f) ? v.w * sc : 0.0f;
    *(float4*)(x + base) = v;
}

// ---------------- output GEMM: out[50000x16] = x @ Wout + bout ----------------
__global__ void out_kernel(const float* __restrict__ x, const float* __restrict__ W,
                           const float* __restrict__ b, float* __restrict__ out, int M) {
    __shared__ float Ws[256 * 16];
    __shared__ float Xs[16 * 256];
    int tid = threadIdx.x;
    int rowBase = blockIdx.x * 16;
    for (int i = tid; i < 256 * 16 / 4; i += 256)
        ((float4*)Ws)[i] = ((const float4*)W)[i];
    for (int i = tid; i < 16 * 64; i += 256) {
        int rr = i >> 6, c4 = i & 63;
        int gr = rowBase + rr;
        float4 v = make_float4(0.f, 0.f, 0.f, 0.f);
        if (gr < M) v = ((const float4*)(x + (size_t)gr * 256))[c4];
        ((float4*)(Xs + rr * 256))[c4] = v;
    }
    __syncthreads();
    int rr = tid >> 4, cc = tid & 15;
    float acc = 0.f;
#pragma unroll 8
    for (int k = 0; k < 256; k++) acc += Xs[rr * 256 + k] * Ws[k * 16 + cc];
    int gr = rowBase + rr;
    if (gr < M) out[(size_t)gr * 16 + cc] = acc + b[cc];
}

// ---------------- host ----------------
extern "C" void kernel_launch(void* const* d_in, const int* in_sizes, int n_in,
                              void* d_out, int out_size) {
    const float* x_source = (const float*)d_in[0];
    const float* x_target = (const float*)d_in[1];
    const int* ei_st = (const int*)d_in[2];  // [0]=src, [1]=dst(target)
    const int* ei_ts = (const int*)d_in[3];  // [0]=src(target), [1]=dst(source)
    const float* Wl_st = (const float*)d_in[4];
    const float* Wr_st = (const float*)d_in[5];
    const float* b_st = (const float*)d_in[6];
    const float* Wl_ts = (const float*)d_in[7];
    const float* Wr_ts = (const float*)d_in[8];
    const float* b_ts = (const float*)d_in[9];
    const float* Wout = (const float*)d_in[10];
    const float* bout = (const float*)d_in[11];
    float* out = (float*)d_out;

    // scratch symbol addresses
    void *p;
    int *cnt_a, *cnt_b, *off_a, *off_b, *csr_a, *csr_b;
    float *mt, *ms, *xs0, *xt0, *xs1, *xt1;
    cudaGetSymbolAddress(&p, g_cnt_a); cnt_a = (int*)p;
    cudaGetSymbolAddress(&p, g_cnt_b); cnt_b = (int*)p;
    cudaGetSymbolAddress(&p, g_off_a); off_a = (int*)p;
    cudaGetSymbolAddress(&p, g_off_b); off_b = (int*)p;
    cudaGetSymbolAddress(&p, g_csr_a); csr_a = (int*)p;
    cudaGetSymbolAddress(&p, g_csr_b); csr_b = (int*)p;
    cudaGetSymbolAddress(&p, g_mt);  mt = (float*)p;
    cudaGetSymbolAddress(&p, g_ms);  ms = (float*)p;
    cudaGetSymbolAddress(&p, g_xs0); xs0 = (float*)p;
    cudaGetSymbolAddress(&p, g_xt0); xt0 = (float*)p;
    cudaGetSymbolAddress(&p, g_xs1); xs1 = (float*)p;
    cudaGetSymbolAddress(&p, g_xt1); xt1 = (float*)p;

    const int* src_st = ei_st;
    const int* dst_st = ei_st + EE;
    const int* src_ts = ei_ts;
    const int* dst_ts = ei_ts + EE;

    // dropout keys: fold_in(key(42)=(0,42), d) for d = 0..3
    // (fold_in uses the raw threefry_2x32 on the seed pair — unchanged by partitionable mode)
    unsigned dkeys[4][2];
    for (int d = 0; d < 4; d++)
        tf2x32(0u, 42u, 0u, (unsigned)d, dkeys[d][0], dkeys[d][1]);

    // ---- CSR build (deterministic graph structure from the edge lists) ----
    zero_kernel<<<(NN + 255) / 256, 256>>>();
    count_kernel<<<(EE + 255) / 256, 256>>>(dst_st, dst_ts);
    scan_kernel<<<1, 1024>>>(cnt_a, off_a);
    scan_kernel<<<1, 1024>>>(cnt_b, off_b);
    fill_kernel<<<(EE + 255) / 256, 256>>>(src_st, dst_st, src_ts, dst_ts);

    dim3 gGrid(2, (NN + 127) / 128);
    const int dropBlocks = (TOT / 4 + 255) / 256;

    // ---- layer 0 ----
    segmean_kernel<<<NN, 64>>>(x_source, off_a, csr_a, mt);
    segmean_kernel<<<NN, 64>>>(x_target, off_b, csr_b, ms);
    gemm_fused<<<gGrid, 256>>>(mt, x_target, Wl_st, Wr_st, b_st, xt0, NN);
    gemm_fused<<<gGrid, 256>>>(ms, x_source, Wl_ts, Wr_ts, b_ts, xs0, NN);
    dropout_kernel<<<dropBlocks, 256>>>(xs0, dkeys[0][0], dkeys[0][1]);
    dropout_kernel<<<dropBlocks, 256>>>(xt0, dkeys[1][0], dkeys[1][1]);

    // ---- layer 1 ----
    segmean_kernel<<<NN, 64>>>(xs0, off_a, csr_a, mt);
    segmean_kernel<<<NN, 64>>>(xt0, off_b, csr_b, ms);
    gemm_fused<<<gGrid, 256>>>(mt, xt0, Wl_st + DD * DD, Wr_st + DD * DD, b_st + DD, xt1, NN);
    gemm_fused<<<gGrid, 256>>>(ms, xs0, Wl_ts + DD * DD, Wr_ts + DD * DD, b_ts + DD, xs1, NN);
    dropout_kernel<<<dropBlocks, 256>>>(xs1, dkeys[2][0], dkeys[2][1]);
    dropout_kernel<<<dropBlocks, 256>>>(xt1, dkeys[3][0], dkeys[3][1]);

    // ---- output projection ----
    out_kernel<<<(NN + 15) / 16, 256>>>(xs1, Wout, bout, out, NN);
}

// round 4
// speedup vs baseline: 1.8328x; 1.8328x over previous
#include <cuda_runtime.h>
#include <cuda_bf16.h>
#include <cstdint>

#define NN 50000
#define DD 256
#define EE 320000
#define TOT (NN * DD)
#define MTILE 128
#define NBLKY ((NN + MTILE - 1) / MTILE)   // 391

// ---------------- scratch (static __device__ — no allocation allowed) ----------------
__device__ int g_cnt_a[NN], g_cnt_b[NN], g_cur_a[NN], g_cur_b[NN];
__device__ int g_off_a[NN + 1], g_off_b[NN + 1];
__device__ int g_csr_a[EE], g_csr_b[EE];
__device__ int g_blk[2][49], g_blkoff[2][49];
__device__ float g_mt[NN * DD], g_ms[NN * DD];
__device__ float g_xs0[NN * DD], g_xt0[NN * DD], g_xs1[NN * DD], g_xt1[NN * DD];
// pre-transposed bf16 hi/lo weights: 8 matrices of [n=256][k=256]
__device__ __nv_bfloat16 g_wbh[8 * 65536], g_wbl[8 * 65536];

// ---------------- threefry-2x32 (exactly JAX's) ----------------
__host__ __device__ __forceinline__ unsigned rotl32(unsigned x, int d) {
    return (x << d) | (x >> (32 - d));
}

__host__ __device__ __forceinline__ void tf2x32(unsigned k0, unsigned k1,
                                                unsigned x0, unsigned x1,
                                                unsigned& o0, unsigned& o1) {
    unsigned ks2 = k0 ^ k1 ^ 0x1BD11BDAu;
    x0 += k0; x1 += k1;
#define TF_ROUND(r) { x0 += x1; x1 = rotl32(x1, r); x1 ^= x0; }
    TF_ROUND(13) TF_ROUND(15) TF_ROUND(26) TF_ROUND(6)
    x0 += k1;  x1 += ks2 + 1u;
    TF_ROUND(17) TF_ROUND(29) TF_ROUND(16) TF_ROUND(24)
    x0 += ks2; x1 += k0 + 2u;
    TF_ROUND(13) TF_ROUND(15) TF_ROUND(26) TF_ROUND(6)
    x0 += k0;  x1 += k1 + 3u;
    TF_ROUND(17) TF_ROUND(29) TF_ROUND(16) TF_ROUND(24)
    x0 += k1;  x1 += ks2 + 4u;
    TF_ROUND(13) TF_ROUND(15) TF_ROUND(26) TF_ROUND(6)
    x0 += ks2; x1 += k0 + 5u;
#undef TF_ROUND
    o0 = x0; o1 = x1;
}

__device__ __forceinline__ unsigned jax_bits32(unsigned k0, unsigned k1, unsigned i) {
    unsigned o0, o1;
    tf2x32(k0, k1, 0u, i, o0, o1);
    return o0 ^ o1;
}

__device__ __forceinline__ uint32_t smem_u32(const void* p) {
    uint32_t a;
    asm("{ .reg .u64 t; cvta.to.shared.u64 t, %1; cvt.u32.u64 %0, t; }" : "=r"(a) : "l"(p));
    return a;
}

// ---------------- CSR build ----------------
__global__ void zero_kernel() {
    int i = blockIdx.x * blockDim.x + threadIdx.x;
    if (i < NN) { g_cnt_a[i] = 0; g_cnt_b[i] = 0; g_cur_a[i] = 0; g_cur_b[i] = 0; }
}

__global__ void count_kernel(const int* __restrict__ dst_a, const int* __restrict__ dst_b) {
    int e = blockIdx.x * blockDim.x + threadIdx.x;
    if (e < EE) {
        atomicAdd(&g_cnt_a[dst_a[e]], 1);
        atomicAdd(&g_cnt_b[dst_b[e]], 1);
    }
}

// 3-phase parallel scan over 50000 counts (grid.y selects array a/b)
__global__ void scan_pre() {
    int y = blockIdx.y;
    const int* cnt = y ? g_cnt_b : g_cnt_a;
    int* off = y ? g_off_b : g_off_a;
    __shared__ int sb[256];
    int t = threadIdx.x;
    int base = blockIdx.x * 1024 + t * 4;
    int v[4]; int s = 0;
#pragma unroll
    for (int i = 0; i < 4; i++) {
        int idx = base + i;
        v[i] = (idx < NN) ? cnt[idx] : 0;
        s += v[i];
    }
    sb[t] = s;
    __syncthreads();
    for (int d = 1; d < 256; d <<= 1) {
        int x = (t >= d) ? sb[t - d] : 0;
        __syncthreads();
        sb[t] += x;
        __syncthreads();
    }
    int run = sb[t] - s;  // exclusive prefix within block
#pragma unroll
    for (int i = 0; i < 4; i++) {
        int idx = base + i;
        if (idx < NN) off[idx] = run;
        run += v[i];
    }
    if (t == 255) g_blk[y][blockIdx.x] = sb[255];
}

__global__ void scan_mid() {
    int y = blockIdx.y;
    int* off = y ? g_off_b : g_off_a;
    __shared__ int sb[64];
    int t = threadIdx.x;
    int v = (t < 49) ? g_blk[y][t] : 0;
    sb[t] = v;
    __syncthreads();
    for (int d = 1; d < 64; d <<= 1) {
        int x = (t >= d) ? sb[t - d] : 0;
        __syncthreads();
        sb[t] += x;
        __syncthreads();
    }
    if (t < 49) g_blkoff[y][t] = sb[t] - v;
    if (t == 63) off[NN] = sb[63];
}

__global__ void scan_add() {
    int y = blockIdx.y;
    int* off = y ? g_off_b : g_off_a;
    int add = g_blkoff[y][blockIdx.x];
    int base = blockIdx.x * 1024 + threadIdx.x * 4;
#pragma unroll
    for (int i = 0; i < 4; i++) {
        int idx = base + i;
        if (idx < NN) off[idx] += add;
    }
}

__global__ void fill_kernel(const int* __restrict__ src_a, const int* __restrict__ dst_a,
                            const int* __restrict__ src_b, const int* __restrict__ dst_b) {
    int e = blockIdx.x * blockDim.x + threadIdx.x;
    if (e < EE) {
        int da = dst_a[e];
        int pa = g_off_a[da] + atomicAdd(&g_cur_a[da], 1);
        g_csr_a[pa] = src_a[e];
        int db = dst_b[e];
        int pb = g_off_b[db] + atomicAdd(&g_cur_b[db], 1);
        g_csr_b[pb] = src_b[e];
    }
}

// ---------------- segment mean ----------------
__global__ void segmean_kernel(const float* __restrict__ x, const int* __restrict__ off,
                               const int* __restrict__ csr, float* __restrict__ out) {
    int r = blockIdx.x;
    int t = threadIdx.x;  // 0..63
    int s0 = off[r], s1 = off[r + 1];
    float4 acc = make_float4(0.f, 0.f, 0.f, 0.f);
    for (int e = s0; e < s1; e++) {
        int src = csr[e];
        float4 v = __ldg((const float4*)(x + (size_t)src * DD) + t);
        acc.x += v.x; acc.y += v.y; acc.z += v.z; acc.w += v.w;
    }
    int cnt = s1 - s0;
    float inv = 1.0f / (float)(cnt > 0 ? cnt : 1);
    acc.x *= inv; acc.y *= inv; acc.z *= inv; acc.w *= inv;
    ((float4*)(out + (size_t)r * DD))[t] = acc;
}

// ---------------- weight prep: transpose + fp32 -> bf16 hi/lo split ----------------
__global__ void wprep_kernel(const float* __restrict__ Wl_st, const float* __restrict__ Wr_st,
                             const float* __restrict__ Wl_ts, const float* __restrict__ Wr_ts) {
    int m = blockIdx.y;           // 0..7
    int layer = m >> 2, t = m & 3;
    const float* base = (t == 0) ? Wl_st : (t == 1) ? Wr_st : (t == 2) ? Wl_ts : Wr_ts;
    const float* W = base + layer * 65536;
    int idx = blockIdx.x * 256 + threadIdx.x;   // n*256 + k, grid.x = 256
    int n = idx >> 8, k = idx & 255;
    float v = W[k * 256 + n];
    __nv_bfloat16 h = __float2bfloat16(v);
    float lo = v - __bfloat162float(h);
    g_wbh[m * 65536 + idx] = h;
    g_wbl[m * 65536 + idx] = __float2bfloat16(lo);
}

// ---------------- mma.sync bf16-split fused dual-GEMM ----------------
// C[M,256] = leaky( A1@W1 + A2@W2 + bias ), W as bf16 hi/lo [n][k]
// x*w ~= xh*wh + xh*wl + xl*wh (fp32 accumulate)
#define ASTRIDE 20            // u32 per row: 16 data + 4 pad (80B, conflict-free ldmatrix)
#define ST_U32 10240          // 4 tiles * 128 rows * 20 u32
#define OFF_AH 0
#define OFF_AL 2560
#define OFF_BH 5120
#define OFF_BL 7680
#define SMEM_GEMM (2 * ST_U32 * 4)   // 81920 B

#define LDSM4(r0, r1, r2, r3, addr) \
    asm volatile("ldmatrix.sync.aligned.m8n8.x4.shared.b16 {%0,%1,%2,%3}, [%4];" \
                 : "=r"(r0), "=r"(r1), "=r"(r2), "=r"(r3) : "r"(addr))

#define MMA16816(c, a, b0, b1) \
    asm volatile("mma.sync.aligned.m16n8k16.row.col.f32.bf16.bf16.f32 " \
                 "{%0,%1,%2,%3}, {%4,%5,%6,%7}, {%8,%9}, {%0,%1,%2,%3};" \
                 : "+f"((c)[0]), "+f"((c)[1]), "+f"((c)[2]), "+f"((c)[3]) \
                 : "r"((a)[0]), "r"((a)[1]), "r"((a)[2]), "r"((a)[3]), "r"(b0), "r"(b1))

__global__ void __launch_bounds__(256, 1) gemm_mma(
    const float* __restrict__ A1, const float* __restrict__ A2,
    const __nv_bfloat16* __restrict__ W1h, const __nv_bfloat16* __restrict__ W1l,
    const __nv_bfloat16* __restrict__ W2h, const __nv_bfloat16* __restrict__ W2l,
    const float* __restrict__ bias, float* __restrict__ C, int M) {
    extern __shared__ uint32_t sm[];
    const int tid = threadIdx.x;
    const int lane = tid & 31, wid = tid >> 5;
    const int warpM = wid & 3, warpN = wid >> 2;      // 4 x 2 warps
    const int rowBase = blockIdx.y * MTILE;
    const int colBase = blockIdx.x * 128;
    const uint32_t smaddr = smem_u32(sm);

    float acc[2][8][4];
#pragma unroll
    for (int i = 0; i < 2; i++)
#pragma unroll
        for (int j = 0; j < 8; j++)
#pragma unroll
            for (int q = 0; q < 4; q++) acc[i][j][q] = 0.f;

    float4 aReg[4];
    uint4 bReg[4];

    // precomputed ldmatrix shared addresses (per-lane, stage 0)
    uint32_t aAddr[2][2], bAddr[4][2];  // [tile][kstep] hi; lo = +OFF delta
#pragma unroll
    for (int mt = 0; mt < 2; mt++)
#pragma unroll
        for (int ks = 0; ks < 2; ks++) {
            int row = warpM * 32 + mt * 16 + (lane & 15);
            int kOff = ks * 16 + (lane >> 4) * 8;
            aAddr[mt][ks] = smaddr + (uint32_t)(OFF_AH + row * ASTRIDE + (kOff >> 1)) * 4;
        }
#pragma unroll
    for (int np = 0; np < 4; np++)
#pragma unroll
        for (int ks = 0; ks < 2; ks++) {
            int n = warpN * 64 + np * 16 + (lane & 7) + (lane >> 4) * 8;
            int kOff = ks * 16 + ((lane >> 3) & 1) * 8;
            bAddr[np][ks] = smaddr + (uint32_t)(OFF_BH + n * ASTRIDE + (kOff >> 1)) * 4;
        }

#define GLOAD(c) do { \
        int mat_ = (c) >> 3; int kb_ = ((c) & 7) * 32; \
        const float* A_ = mat_ ? A2 : A1; \
        const __nv_bfloat16* Bh_ = mat_ ? W2h : W1h; \
        const __nv_bfloat16* Bl_ = mat_ ? W2l : W1l; \
        _Pragma("unroll") \
        for (int j = 0; j < 4; j++) { \
            int idx = tid + j * 256; \
            int r = idx >> 3, kq = (idx & 7) * 4; \
            int gr = rowBase + r; \
            aReg[j] = (gr < M) ? *(const float4*)(A_ + (size_t)gr * 256 + kb_ + kq) \
                               : make_float4(0.f, 0.f, 0.f, 0.f); \
        } \
        _Pragma("unroll") \
        for (int j = 0; j < 2; j++) { \
            int idx = tid + j * 256; \
            int n = idx >> 2, ko = (idx & 3) * 8; \
            bReg[j]     = *(const uint4*)(Bh_ + (size_t)(colBase + n) * 256 + kb_ + ko); \
            bReg[2 + j] = *(const uint4*)(Bl_ + (size_t)(colBase + n) * 256 + kb_ + ko); \
        } \
    } while (0)

#define SSTORE(st) do { \
        uint32_t* base_ = sm + (st) * ST_U32; \
        _Pragma("unroll") \
        for (int j = 0; j < 4; j++) { \
            int idx = tid + j * 256; \
            int r = idx >> 3, kq = (idx & 7) * 4; \
            float4 v = aReg[j]; \
            __nv_bfloat162 h01 = __floats2bfloat162_rn(v.x, v.y); \
            __nv_bfloat162 h23 = __floats2bfloat162_rn(v.z, v.w); \
            float lx = v.x - __bfloat162float(h01.x); \
            float ly = v.y - __bfloat162float(h01.y); \
            float lz = v.z - __bfloat162float(h23.x); \
            float lw = v.w - __bfloat162float(h23.y); \
            __nv_bfloat162 l01 = __floats2bfloat162_rn(lx, ly); \
            __nv_bfloat162 l23 = __floats2bfloat162_rn(lz, lw); \
            uint32_t off = (uint32_t)(r * ASTRIDE + (kq >> 1)); \
            base_[OFF_AH + off]     = *(uint32_t*)&h01; \
            base_[OFF_AH + off + 1] = *(uint32_t*)&h23; \
            base_[OFF_AL + off]     = *(uint32_t*)&l01; \
            base_[OFF_AL + off + 1] = *(uint32_t*)&l23; \
        } \
        _Pragma("unroll") \
        for (int j = 0; j < 2; j++) { \
            int idx = tid + j * 256; \
            int n = idx >> 2, ko = (idx & 3) * 8; \
            uint32_t off = (uint32_t)(n * ASTRIDE + (ko >> 1)); \
            *(uint4*)(base_ + OFF_BH + off) = bReg[j]; \
            *(uint4*)(base_ + OFF_BL + off) = bReg[2 + j]; \
        } \
    } while (0)

    GLOAD(0);
    SSTORE(0);
    __syncthreads();

#pragma unroll 1
    for (int c = 0; c < 16; c++) {
        const int st = c & 1;
        if (c < 15) GLOAD(c + 1);
        const uint32_t stOff = (uint32_t)(st * ST_U32 * 4);
#pragma unroll
        for (int ks = 0; ks < 2; ks++) {
            uint32_t ah[2][4], al[2][4], bh[4][4], bl[4][4];
#pragma unroll
            for (int mt = 0; mt < 2; mt++) {
                uint32_t ad = aAddr[mt][ks] + stOff;
                LDSM4(ah[mt][0], ah[mt][1], ah[mt][2], ah[mt][3], ad);
                LDSM4(al[mt][0], al[mt][1], al[mt][2], al[mt][3], ad + (OFF_AL - OFF_AH) * 4);
            }
#pragma unroll
            for (int np = 0; np < 4; np++) {
                uint32_t bd = bAddr[np][ks] + stOff;
                LDSM4(bh[np][0], bh[np][1], bh[np][2], bh[np][3], bd);
                LDSM4(bl[np][0], bl[np][1], bl[np][2], bl[np][3], bd + (OFF_BL - OFF_BH) * 4);
            }
#pragma unroll
            for (int mt = 0; mt < 2; mt++)
#pragma unroll
                for (int nt = 0; nt < 8; nt++) {
                    int grp = nt >> 1, pr = (nt & 1) * 2;
                    MMA16816(acc[mt][nt], ah[mt], bh[grp][pr], bh[grp][pr + 1]);
                    MMA16816(acc[mt][nt], ah[mt], bl[grp][pr], bl[grp][pr + 1]);
                    MMA16816(acc[mt][nt], al[mt], bh[grp][pr], bh[grp][pr + 1]);
                }
        }
        if (c < 15) {
            __syncthreads();
            SSTORE((c + 1) & 1);
            __syncthreads();
        }
    }

    // epilogue: bias + leaky-relu, direct global store
#pragma unroll
    for (int mt = 0; mt < 2; mt++)
#pragma unroll
        for (int nt = 0; nt < 8; nt++) {
            int col = colBase + warpN * 64 + nt * 8 + (lane & 3) * 2;
            float2 bv = *(const float2*)(bias + col);
            int r0 = rowBase + warpM * 32 + mt * 16 + (lane >> 2);
            float v0 = acc[mt][nt][0] + bv.x;
            float v1 = acc[mt][nt][1] + bv.y;
            v0 = v0 >= 0.f ? v0 : 0.01f * v0;
            v1 = v1 >= 0.f ? v1 : 0.01f * v1;
            if (r0 < M) *(float2*)(C + (size_t)r0 * 256 + col) = make_float2(v0, v1);
            int r1 = r0 + 8;
            float v2 = acc[mt][nt][2] + bv.x;
            float v3 = acc[mt][nt][3] + bv.y;
            v2 = v2 >= 0.f ? v2 : 0.01f * v2;
            v3 = v3 >= 0.f ? v3 : 0.01f * v3;
            if (r1 < M) *(float2*)(C + (size_t)r1 * 256 + col) = make_float2(v2, v3);
        }
}

// ---------------- dropout: JAX partitionable threefry, bit-exact ----------------
__global__ __launch_bounds__(256) void dropout_kernel(float* __restrict__ x,
                                                      unsigned k0, unsigned k1) {
    int base = (blockIdx.x * blockDim.x + threadIdx.x) * 4;
    if (base >= TOT) return;
    float4 v = *(float4*)(x + base);
    const float sc = 1.0f / 0.9f;
    unsigned b0 = jax_bits32(k0, k1, (unsigned)(base + 0));
    unsigned b1 = jax_bits32(k0, k1, (unsigned)(base + 1));
    unsigned b2 = jax_bits32(k0, k1, (unsigned)(base + 2));
    unsigned b3 = jax_bits32(k0, k1, (unsigned)(base + 3));
    float u0 = __uint_as_float((b0 >> 9) | 0x3f800000u) - 1.0f;
    float u1 = __uint_as_float((b1 >> 9) | 0x3f800000u) - 1.0f;
    float u2 = __uint_as_float((b2 >> 9) | 0x3f800000u) - 1.0f;
    float u3 = __uint_as_float((b3 >> 9) | 0x3f800000u) - 1.0f;
    v.x = (u0 < 0.9f) ? v.x * sc : 0.0f;
    v.y = (u1 < 0.9f) ? v.y * sc : 0.0f;
    v.z = (u2 < 0.9f) ? v.z * sc : 0.0f;
    v.w = (u3 < 0.9f) ? v.w * sc : 0.0f;
    *(float4*)(x + base) = v;
}

// ---------------- output GEMM: out[50000x16] = x @ Wout + bout ----------------
__global__ void out_kernel(const float* __restrict__ x, const float* __restrict__ W,
                           const float* __restrict__ b, float* __restrict__ out, int M) {
    __shared__ float Ws[256 * 16];
    __shared__ float Xs[16 * 256];
    int tid = threadIdx.x;
    int rowBase = blockIdx.x * 16;
    for (int i = tid; i < 256 * 16 / 4; i += 256)
        ((float4*)Ws)[i] = ((const float4*)W)[i];
    for (int i = tid; i < 16 * 64; i += 256) {
        int rr = i >> 6, c4 = i & 63;
        int gr = rowBase + rr;
        float4 v = make_float4(0.f, 0.f, 0.f, 0.f);
        if (gr < M) v = ((const float4*)(x + (size_t)gr * 256))[c4];
        ((float4*)(Xs + rr * 256))[c4] = v;
    }
    __syncthreads();
    int rr = tid >> 4, cc = tid & 15;
    float acc = 0.f;
#pragma unroll 8
    for (int k = 0; k < 256; k++) acc += Xs[rr * 256 + k] * Ws[k * 16 + cc];
    int gr = rowBase + rr;
    if (gr < M) out[(size_t)gr * 16 + cc] = acc + b[cc];
}

// ---------------- host ----------------
extern "C" void kernel_launch(void* const* d_in, const int* in_sizes, int n_in,
                              void* d_out, int out_size) {
    const float* x_source = (const float*)d_in[0];
    const float* x_target = (const float*)d_in[1];
    const int* ei_st = (const int*)d_in[2];
    const int* ei_ts = (const int*)d_in[3];
    const float* Wl_st = (const float*)d_in[4];
    const float* Wr_st = (const float*)d_in[5];
    const float* b_st = (const float*)d_in[6];
    const float* Wl_ts = (const float*)d_in[7];
    const float* Wr_ts = (const float*)d_in[8];
    const float* b_ts = (const float*)d_in[9];
    const float* Wout = (const float*)d_in[10];
    const float* bout = (const float*)d_in[11];
    float* out = (float*)d_out;

    void* p;
    float *mt, *ms, *xs0, *xt0, *xs1, *xt1;
    __nv_bfloat16 *wbh, *wbl;
    cudaGetSymbolAddress(&p, g_mt);  mt = (float*)p;
    cudaGetSymbolAddress(&p, g_ms);  ms = (float*)p;
    cudaGetSymbolAddress(&p, g_xs0); xs0 = (float*)p;
    cudaGetSymbolAddress(&p, g_xt0); xt0 = (float*)p;
    cudaGetSymbolAddress(&p, g_xs1); xs1 = (float*)p;
    cudaGetSymbolAddress(&p, g_xt1); xt1 = (float*)p;
    cudaGetSymbolAddress(&p, g_wbh); wbh = (__nv_bfloat16*)p;
    cudaGetSymbolAddress(&p, g_wbl); wbl = (__nv_bfloat16*)p;
    int *off_a, *off_b, *csr_a, *csr_b;
    cudaGetSymbolAddress(&p, g_off_a); off_a = (int*)p;
    cudaGetSymbolAddress(&p, g_off_b); off_b = (int*)p;
    cudaGetSymbolAddress(&p, g_csr_a); csr_a = (int*)p;
    cudaGetSymbolAddress(&p, g_csr_b); csr_b = (int*)p;

    cudaFuncSetAttribute(gemm_mma, cudaFuncAttributeMaxDynamicSharedMemorySize, SMEM_GEMM);

    const int* src_st = ei_st;
    const int* dst_st = ei_st + EE;
    const int* src_ts = ei_ts;
    const int* dst_ts = ei_ts + EE;

    unsigned dkeys[4][2];
    for (int d = 0; d < 4; d++)
        tf2x32(0u, 42u, 0u, (unsigned)d, dkeys[d][0], dkeys[d][1]);

    // weight prep (transpose + bf16 split): 8 matrices
    wprep_kernel<<<dim3(256, 8), 256>>>(Wl_st, Wr_st, Wl_ts, Wr_ts);

    // CSR build
    zero_kernel<<<(NN + 255) / 256, 256>>>();
    count_kernel<<<(EE + 255) / 256, 256>>>(dst_st, dst_ts);
    scan_pre<<<dim3(49, 2), 256>>>();
    scan_mid<<<dim3(1, 2), 64>>>();
    scan_add<<<dim3(49, 2), 256>>>();
    fill_kernel<<<(EE + 255) / 256, 256>>>(src_st, dst_st, src_ts, dst_ts);

    const int dropBlocks = (TOT / 4 + 255) / 256;
    const int M64K = 65536;
    dim3 gGrid(2, NBLKY);

    // ---- layer 0 ----
    segmean_kernel<<<NN, 64>>>(x_source, off_a, csr_a, mt);
    segmean_kernel<<<NN, 64>>>(x_target, off_b, csr_b, ms);
    gemm_mma<<<gGrid, 256, SMEM_GEMM>>>(mt, x_target, wbh + 0 * M64K, wbl + 0 * M64K,
                                        wbh + 1 * M64K, wbl + 1 * M64K, b_st, xt0, NN);
    gemm_mma<<<gGrid, 256, SMEM_GEMM>>>(ms, x_source, wbh + 2 * M64K, wbl + 2 * M64K,
                                        wbh + 3 * M64K, wbl + 3 * M64K, b_ts, xs0, NN);
    dropout_kernel<<<dropBlocks, 256>>>(xs0, dkeys[0][0], dkeys[0][1]);
    dropout_kernel<<<dropBlocks, 256>>>(xt0, dkeys[1][0], dkeys[1][1]);

    // ---- layer 1 ----
    segmean_kernel<<<NN, 64>>>(xs0, off_a, csr_a, mt);
    segmean_kernel<<<NN, 64>>>(xt0, off_b, csr_b, ms);
    gemm_mma<<<gGrid, 256, SMEM_GEMM>>>(mt, xt0, wbh + 4 * M64K, wbl + 4 * M64K,
                                        wbh + 5 * M64K, wbl + 5 * M64K, b_st + 256, xt1, NN);
    gemm_mma<<<gGrid, 256, SMEM_GEMM>>>(ms, xs0, wbh + 6 * M64K, wbl + 6 * M64K,
                                        wbh + 7 * M64K, wbl + 7 * M64K, b_ts + 256, xs1, NN);
    dropout_kernel<<<dropBlocks, 256>>>(xs1, dkeys[2][0], dkeys[2][1]);
    dropout_kernel<<<dropBlocks, 256>>>(xt1, dkeys[3][0], dkeys[3][1]);

    // ---- output projection ----
    out_kernel<<<(NN + 15) / 16, 256>>>(xs1, Wout, bout, out, NN);
}

// round 5
// speedup vs baseline: 2.2902x; 1.2496x over previous
#include <cuda_runtime.h>
#include <cuda_bf16.h>
#include <cstdint>

#define NN 50000
#define DD 256
#define EE 320000
#define TOT (NN * DD)
#define MTILE 128
#define NBLKY ((NN + MTILE - 1) / MTILE)   // 391

// ---------------- scratch (static __device__ — no allocation allowed) ----------------
__device__ int g_cnt_a[NN], g_cnt_b[NN], g_cur_a[NN], g_cur_b[NN];
__device__ int g_off_a[NN + 1], g_off_b[NN + 1];
__device__ int g_csr_a[EE], g_csr_b[EE];
__device__ int g_blk[2][49], g_blkoff[2][49];
// packed bf16-split activations: u32 = hi | lo<<16
__device__ unsigned g_pxs[TOT], g_pxt[TOT];       // converted inputs
__device__ unsigned g_pma[TOT], g_pmb[TOT];       // segment means
__device__ unsigned g_pxt0[TOT], g_pxs0[TOT], g_pxs1[TOT];
// pre-transposed bf16 hi/lo weights: 8 matrices of [n=256][k=256]
__device__ __nv_bfloat16 g_wbh[8 * 65536], g_wbl[8 * 65536];

// ---------------- threefry-2x32 (exactly JAX's) ----------------
__host__ __device__ __forceinline__ unsigned rotl32(unsigned x, int d) {
    return (x << d) | (x >> (32 - d));
}

__host__ __device__ __forceinline__ void tf2x32(unsigned k0, unsigned k1,
                                                unsigned x0, unsigned x1,
                                                unsigned& o0, unsigned& o1) {
    unsigned ks2 = k0 ^ k1 ^ 0x1BD11BDAu;
    x0 += k0; x1 += k1;
#define TF_ROUND(r) { x0 += x1; x1 = rotl32(x1, r); x1 ^= x0; }
    TF_ROUND(13) TF_ROUND(15) TF_ROUND(26) TF_ROUND(6)
    x0 += k1;  x1 += ks2 + 1u;
    TF_ROUND(17) TF_ROUND(29) TF_ROUND(16) TF_ROUND(24)
    x0 += ks2; x1 += k0 + 2u;
    TF_ROUND(13) TF_ROUND(15) TF_ROUND(26) TF_ROUND(6)
    x0 += k0;  x1 += k1 + 3u;
    TF_ROUND(17) TF_ROUND(29) TF_ROUND(16) TF_ROUND(24)
    x0 += k1;  x1 += ks2 + 4u;
    TF_ROUND(13) TF_ROUND(15) TF_ROUND(26) TF_ROUND(6)
    x0 += ks2; x1 += k0 + 5u;
#undef TF_ROUND
    o0 = x0; o1 = x1;
}

__device__ __forceinline__ unsigned jax_bits32(unsigned k0, unsigned k1, unsigned i) {
    unsigned o0, o1;
    tf2x32(k0, k1, 0u, i, o0, o1);
    return o0 ^ o1;
}

__device__ __forceinline__ uint32_t smem_u32(const void* p) {
    uint32_t a;
    asm("{ .reg .u64 t; cvta.to.shared.u64 t, %1; cvt.u32.u64 %0, t; }" : "=r"(a) : "l"(p));
    return a;
}

// ---------------- packed bf16-split helpers ----------------
__device__ __forceinline__ unsigned pack_split(float v) {
    __nv_bfloat16 h = __float2bfloat16(v);
    unsigned hu = (unsigned)*(unsigned short*)&h;
    float hf = __uint_as_float(hu << 16);
    __nv_bfloat16 l = __float2bfloat16(v - hf);
    unsigned lu = (unsigned)*(unsigned short*)&l;
    return hu | (lu << 16);
}

__device__ __forceinline__ float unpack_val(unsigned p) {
    return __uint_as_float(p << 16) + __uint_as_float(p & 0xFFFF0000u);
}

// ---------------- CSR build ----------------
__global__ void zero_kernel() {
    int i = blockIdx.x * blockDim.x + threadIdx.x;
    if (i < NN) { g_cnt_a[i] = 0; g_cnt_b[i] = 0; g_cur_a[i] = 0; g_cur_b[i] = 0; }
}

__global__ void count_kernel(const int* __restrict__ dst_a, const int* __restrict__ dst_b) {
    int e = blockIdx.x * blockDim.x + threadIdx.x;
    if (e < EE) {
        atomicAdd(&g_cnt_a[dst_a[e]], 1);
        atomicAdd(&g_cnt_b[dst_b[e]], 1);
    }
}

__global__ void scan_pre() {
    int y = blockIdx.y;
    const int* cnt = y ? g_cnt_b : g_cnt_a;
    int* off = y ? g_off_b : g_off_a;
    __shared__ int sb[256];
    int t = threadIdx.x;
    int base = blockIdx.x * 1024 + t * 4;
    int v[4]; int s = 0;
#pragma unroll
    for (int i = 0; i < 4; i++) {
        int idx = base + i;
        v[i] = (idx < NN) ? cnt[idx] : 0;
        s += v[i];
    }
    sb[t] = s;
    __syncthreads();
    for (int d = 1; d < 256; d <<= 1) {
        int x = (t >= d) ? sb[t - d] : 0;
        __syncthreads();
        sb[t] += x;
        __syncthreads();
    }
    int run = sb[t] - s;
#pragma unroll
    for (int i = 0; i < 4; i++) {
        int idx = base + i;
        if (idx < NN) off[idx] = run;
        run += v[i];
    }
    if (t == 255) g_blk[y][blockIdx.x] = sb[255];
}

__global__ void scan_mid() {
    int y = blockIdx.y;
    int* off = y ? g_off_b : g_off_a;
    __shared__ int sb[64];
    int t = threadIdx.x;
    int v = (t < 49) ? g_blk[y][t] : 0;
    sb[t] = v;
    __syncthreads();
    for (int d = 1; d < 64; d <<= 1) {
        int x = (t >= d) ? sb[t - d] : 0;
        __syncthreads();
        sb[t] += x;
        __syncthreads();
    }
    if (t < 49) g_blkoff[y][t] = sb[t] - v;
    if (t == 63) off[NN] = sb[63];
}

__global__ void scan_add() {
    int y = blockIdx.y;
    int* off = y ? g_off_b : g_off_a;
    int add = g_blkoff[y][blockIdx.x];
    int base = blockIdx.x * 1024 + threadIdx.x * 4;
#pragma unroll
    for (int i = 0; i < 4; i++) {
        int idx = base + i;
        if (idx < NN) off[idx] += add;
    }
}

__global__ void fill_kernel(const int* __restrict__ src_a, const int* __restrict__ dst_a,
                            const int* __restrict__ src_b, const int* __restrict__ dst_b) {
    int e = blockIdx.x * blockDim.x + threadIdx.x;
    if (e < EE) {
        int da = dst_a[e];
        int pa = g_off_a[da] + atomicAdd(&g_cur_a[da], 1);
        g_csr_a[pa] = src_a[e];
        int db = dst_b[e];
        int pb = g_off_b[db] + atomicAdd(&g_cur_b[db], 1);
        g_csr_b[pb] = src_b[e];
    }
}

// ---------------- input conversion fp32 -> packed ----------------
__global__ void conv_kernel(const float* __restrict__ xs, const float* __restrict__ xt) {
    int i = blockIdx.x * 256 + threadIdx.x;
    int base = i * 4;
    if (base >= TOT) return;
    const float* src = blockIdx.y ? xt : xs;
    unsigned* dst = blockIdx.y ? g_pxt : g_pxs;
    float4 v = *(const float4*)(src + base);
    uint4 o;
    o.x = pack_split(v.x); o.y = pack_split(v.y);
    o.z = pack_split(v.z); o.w = pack_split(v.w);
    *(uint4*)(dst + base) = o;
}

// ---------------- segment mean over packed activations ----------------
__global__ void segmean_kernel(const unsigned* __restrict__ x, const int* __restrict__ off,
                               const int* __restrict__ csr, unsigned* __restrict__ out) {
    int r = blockIdx.x;
    int t = threadIdx.x;  // 0..63, 4 elements each
    int s0 = off[r], s1 = off[r + 1];
    float a0 = 0.f, a1 = 0.f, a2 = 0.f, a3 = 0.f;
    for (int e = s0; e < s1; e++) {
        int src = csr[e];
        uint4 p = __ldg((const uint4*)(x + (size_t)src * DD) + t);
        a0 += unpack_val(p.x); a1 += unpack_val(p.y);
        a2 += unpack_val(p.z); a3 += unpack_val(p.w);
    }
    int cnt = s1 - s0;
    float inv = 1.0f / (float)(cnt > 0 ? cnt : 1);
    uint4 o;
    o.x = pack_split(a0 * inv); o.y = pack_split(a1 * inv);
    o.z = pack_split(a2 * inv); o.w = pack_split(a3 * inv);
    ((uint4*)(out + (size_t)r * DD))[t] = o;
}

// ---------------- weight prep: transpose + fp32 -> bf16 hi/lo split ----------------
__global__ void wprep_kernel(const float* __restrict__ Wl_st, const float* __restrict__ Wr_st,
                             const float* __restrict__ Wl_ts, const float* __restrict__ Wr_ts) {
    int m = blockIdx.y;           // 0..7
    int layer = m >> 2, t = m & 3;
    const float* base = (t == 0) ? Wl_st : (t == 1) ? Wr_st : (t == 2) ? Wl_ts : Wr_ts;
    const float* W = base + layer * 65536;
    int idx = blockIdx.x * 256 + threadIdx.x;
    int n = idx >> 8, k = idx & 255;
    float v = W[k * 256 + n];
    __nv_bfloat16 h = __float2bfloat16(v);
    float lo = v - __bfloat162float(h);
    g_wbh[m * 65536 + idx] = h;
    g_wbl[m * 65536 + idx] = __float2bfloat16(lo);
}

// ---------------- mma.sync bf16-split fused dual-GEMM + bias + leaky + dropout ----------------
// C_packed[M,256] = pack( dropout( leaky( A1@W1 + A2@W2 + bias ) ) )
// A given packed (hi|lo<<16); W as bf16 hi/lo [n][k]; x*w ~= xh*wh + xh*wl + xl*wh
#define ASTRIDE 20
#define ST_U32 10240
#define OFF_AH 0
#define OFF_AL 2560
#define OFF_BH 5120
#define OFF_BL 7680
#define SMEM_GEMM (2 * ST_U32 * 4)   // 81920 B

#define LDSM4(r0, r1, r2, r3, addr) \
    asm volatile("ldmatrix.sync.aligned.m8n8.x4.shared.b16 {%0,%1,%2,%3}, [%4];" \
                 : "=r"(r0), "=r"(r1), "=r"(r2), "=r"(r3) : "r"(addr))

#define MMA16816(c, a, b0, b1) \
    asm volatile("mma.sync.aligned.m16n8k16.row.col.f32.bf16.bf16.f32 " \
                 "{%0,%1,%2,%3}, {%4,%5,%6,%7}, {%8,%9}, {%0,%1,%2,%3};" \
                 : "+f"((c)[0]), "+f"((c)[1]), "+f"((c)[2]), "+f"((c)[3]) \
                 : "r"((a)[0]), "r"((a)[1]), "r"((a)[2]), "r"((a)[3]), "r"(b0), "r"(b1))

__global__ void __launch_bounds__(256, 1) gemm_mma(
    const unsigned* __restrict__ A1, const unsigned* __restrict__ A2,
    const __nv_bfloat16* __restrict__ W1h, const __nv_bfloat16* __restrict__ W1l,
    const __nv_bfloat16* __restrict__ W2h, const __nv_bfloat16* __restrict__ W2l,
    const float* __restrict__ bias, unsigned* __restrict__ C, int M,
    unsigned dk0, unsigned dk1) {
    extern __shared__ uint32_t sm[];
    const int tid = threadIdx.x;
    const int lane = tid & 31, wid = tid >> 5;
    const int warpM = wid & 3, warpN = wid >> 2;      // 4 x 2 warps
    const int rowBase = blockIdx.y * MTILE;
    const int colBase = blockIdx.x * 128;
    const uint32_t smaddr = smem_u32(sm);

    float acc[2][8][4];
#pragma unroll
    for (int i = 0; i < 2; i++)
#pragma unroll
        for (int j = 0; j < 8; j++)
#pragma unroll
            for (int q = 0; q < 4; q++) acc[i][j][q] = 0.f;

    uint4 aReg[4];
    uint4 bReg[4];

    uint32_t aAddr[2][2], bAddr[4][2];
#pragma unroll
    for (int mt = 0; mt < 2; mt++)
#pragma unroll
        for (int ks = 0; ks < 2; ks++) {
            int row = warpM * 32 + mt * 16 + (lane & 15);
            int kOff = ks * 16 + (lane >> 4) * 8;
            aAddr[mt][ks] = smaddr + (uint32_t)(OFF_AH + row * ASTRIDE + (kOff >> 1)) * 4;
        }
#pragma unroll
    for (int np = 0; np < 4; np++)
#pragma unroll
        for (int ks = 0; ks < 2; ks++) {
            int n = warpN * 64 + np * 16 + (lane & 7) + (lane >> 4) * 8;
            int kOff = ks * 16 + ((lane >> 3) & 1) * 8;
            bAddr[np][ks] = smaddr + (uint32_t)(OFF_BH + n * ASTRIDE + (kOff >> 1)) * 4;
        }

#define GLOAD(c) do { \
        int mat_ = (c) >> 3; int kb_ = ((c) & 7) * 32; \
        const unsigned* A_ = mat_ ? A2 : A1; \
        const __nv_bfloat16* Bh_ = mat_ ? W2h : W1h; \
        const __nv_bfloat16* Bl_ = mat_ ? W2l : W1l; \
        _Pragma("unroll") \
        for (int j = 0; j < 4; j++) { \
            int idx = tid + j * 256; \
            int r = idx >> 3, kq = (idx & 7) * 4; \
            int gr = rowBase + r; \
            aReg[j] = (gr < M) ? *(const uint4*)(A_ + (size_t)gr * 256 + kb_ + kq) \
                               : make_uint4(0u, 0u, 0u, 0u); \
        } \
        _Pragma("unroll") \
        for (int j = 0; j < 2; j++) { \
            int idx = tid + j * 256; \
            int n = idx >> 2, ko = (idx & 3) * 8; \
            bReg[j]     = *(const uint4*)(Bh_ + (size_t)(colBase + n) * 256 + kb_ + ko); \
            bReg[2 + j] = *(const uint4*)(Bl_ + (size_t)(colBase + n) * 256 + kb_ + ko); \
        } \
    } while (0)

#define SSTORE(st) do { \
        uint32_t* base_ = sm + (st) * ST_U32; \
        _Pragma("unroll") \
        for (int j = 0; j < 4; j++) { \
            int idx = tid + j * 256; \
            int r = idx >> 3, kq = (idx & 7) * 4; \
            uint4 p = aReg[j]; \
            uint32_t ah01 = __byte_perm(p.x, p.y, 0x5410); \
            uint32_t al01 = __byte_perm(p.x, p.y, 0x7632); \
            uint32_t ah23 = __byte_perm(p.z, p.w, 0x5410); \
            uint32_t al23 = __byte_perm(p.z, p.w, 0x7632); \
            uint32_t off = (uint32_t)(r * ASTRIDE + (kq >> 1)); \
            base_[OFF_AH + off]     = ah01; \
            base_[OFF_AH + off + 1] = ah23; \
            base_[OFF_AL + off]     = al01; \
            base_[OFF_AL + off + 1] = al23; \
        } \
        _Pragma("unroll") \
        for (int j = 0; j < 2; j++) { \
            int idx = tid + j * 256; \
            int n = idx >> 2, ko = (idx & 3) * 8; \
            uint32_t off = (uint32_t)(n * ASTRIDE + (ko >> 1)); \
            *(uint4*)(base_ + OFF_BH + off) = bReg[j]; \
            *(uint4*)(base_ + OFF_BL + off) = bReg[2 + j]; \
        } \
    } while (0)

    GLOAD(0);
    SSTORE(0);
    __syncthreads();

#pragma unroll 1
    for (int c = 0; c < 16; c++) {
        const int st = c & 1;
        if (c < 15) GLOAD(c + 1);
        const uint32_t stOff = (uint32_t)(st * ST_U32 * 4);
#pragma unroll
        for (int ks = 0; ks < 2; ks++) {
            uint32_t ah[2][4], al[2][4], bh[4][4], bl[4][4];
#pragma unroll
            for (int mt = 0; mt < 2; mt++) {
                uint32_t ad = aAddr[mt][ks] + stOff;
                LDSM4(ah[mt][0], ah[mt][1], ah[mt][2], ah[mt][3], ad);
                LDSM4(al[mt][0], al[mt][1], al[mt][2], al[mt][3], ad + (OFF_AL - OFF_AH) * 4);
            }
#pragma unroll
            for (int np = 0; np < 4; np++) {
                uint32_t bd = bAddr[np][ks] + stOff;
                LDSM4(bh[np][0], bh[np][1], bh[np][2], bh[np][3], bd);
                LDSM4(bl[np][0], bl[np][1], bl[np][2], bl[np][3], bd + (OFF_BL - OFF_BH) * 4);
            }
#pragma unroll
            for (int mt = 0; mt < 2; mt++)
#pragma unroll
                for (int nt = 0; nt < 8; nt++) {
                    int grp = nt >> 1, pr = (nt & 1) * 2;
                    MMA16816(acc[mt][nt], ah[mt], bh[grp][pr], bh[grp][pr + 1]);
                    MMA16816(acc[mt][nt], ah[mt], bl[grp][pr], bl[grp][pr + 1]);
                    MMA16816(acc[mt][nt], al[mt], bh[grp][pr], bh[grp][pr + 1]);
                }
        }
        if (c < 15) {
            __syncthreads();
            SSTORE((c + 1) & 1);
            __syncthreads();
        }
    }

    // epilogue: bias + leaky-relu + dropout + pack, store packed u32
    const float sc = 1.0f / 0.9f;
#pragma unroll
    for (int mt = 0; mt < 2; mt++)
#pragma unroll
        for (int nt = 0; nt < 8; nt++) {
            int col = colBase + warpN * 64 + nt * 8 + (lane & 3) * 2;
            float2 bv = *(const float2*)(bias + col);
            int r0 = rowBase + warpM * 32 + mt * 16 + (lane >> 2);
            int r1 = r0 + 8;
            float v0 = acc[mt][nt][0] + bv.x;
            float v1 = acc[mt][nt][1] + bv.y;
            float v2 = acc[mt][nt][2] + bv.x;
            float v3 = acc[mt][nt][3] + bv.y;
            v0 = v0 >= 0.f ? v0 : 0.01f * v0;
            v1 = v1 >= 0.f ? v1 : 0.01f * v1;
            v2 = v2 >= 0.f ? v2 : 0.01f * v2;
            v3 = v3 >= 0.f ? v3 : 0.01f * v3;
            if (r0 < M) {
                unsigned i0 = (unsigned)r0 * 256u + (unsigned)col;
                unsigned q0 = jax_bits32(dk0, dk1, i0);
                unsigned q1 = jax_bits32(dk0, dk1, i0 + 1u);
                float u0 = __uint_as_float((q0 >> 9) | 0x3f800000u) - 1.0f;
                float u1 = __uint_as_float((q1 >> 9) | 0x3f800000u) - 1.0f;
                v0 = (u0 < 0.9f) ? v0 * sc : 0.0f;
                v1 = (u1 < 0.9f) ? v1 * sc : 0.0f;
                uint2 w = make_uint2(pack_split(v0), pack_split(v1));
                *(uint2*)(C + (size_t)r0 * 256 + col) = w;
            }
            if (r1 < M) {
                unsigned i1 = (unsigned)r1 * 256u + (unsigned)col;
                unsigned q2 = jax_bits32(dk0, dk1, i1);
                unsigned q3 = jax_bits32(dk0, dk1, i1 + 1u);
                float u2 = __uint_as_float((q2 >> 9) | 0x3f800000u) - 1.0f;
                float u3 = __uint_as_float((q3 >> 9) | 0x3f800000u) - 1.0f;
                v2 = (u2 < 0.9f) ? v2 * sc : 0.0f;
                v3 = (u3 < 0.9f) ? v3 * sc : 0.0f;
                uint2 w = make_uint2(pack_split(v2), pack_split(v3));
                *(uint2*)(C + (size_t)r1 * 256 + col) = w;
            }
        }
}

// ---------------- output GEMM: out[50000x16] = unpack(x) @ Wout + bout ----------------
__global__ void out_kernel(const unsigned* __restrict__ x, const float* __restrict__ W,
                           const float* __restrict__ b, float* __restrict__ out, int M) {
    __shared__ float Ws[256 * 16];
    __shared__ float Xs[16 * 256];
    int tid = threadIdx.x;
    int rowBase = blockIdx.x * 16;
    for (int i = tid; i < 256 * 16 / 4; i += 256)
        ((float4*)Ws)[i] = ((const float4*)W)[i];
    for (int i = tid; i < 16 * 64; i += 256) {
        int rr = i >> 6, c4 = i & 63;
        int gr = rowBase + rr;
        float4 v = make_float4(0.f, 0.f, 0.f, 0.f);
        if (gr < M) {
            uint4 p = ((const uint4*)(x + (size_t)gr * 256))[c4];
            v.x = unpack_val(p.x); v.y = unpack_val(p.y);
            v.z = unpack_val(p.z); v.w = unpack_val(p.w);
        }
        ((float4*)(Xs + rr * 256))[c4] = v;
    }
    __syncthreads();
    int rr = tid >> 4, cc = tid & 15;
    float acc = 0.f;
#pragma unroll 8
    for (int k = 0; k < 256; k++) acc += Xs[rr * 256 + k] * Ws[k * 16 + cc];
    int gr = rowBase + rr;
    if (gr < M) out[(size_t)gr * 16 + cc] = acc + b[cc];
}

// ---------------- host ----------------
extern "C" void kernel_launch(void* const* d_in, const int* in_sizes, int n_in,
                              void* d_out, int out_size) {
    const float* x_source = (const float*)d_in[0];
    const float* x_target = (const float*)d_in[1];
    const int* ei_st = (const int*)d_in[2];
    const int* ei_ts = (const int*)d_in[3];
    const float* Wl_st = (const float*)d_in[4];
    const float* Wr_st = (const float*)d_in[5];
    const float* b_st = (const float*)d_in[6];
    const float* Wl_ts = (const float*)d_in[7];
    const float* Wr_ts = (const float*)d_in[8];
    const float* b_ts = (const float*)d_in[9];
    const float* Wout = (const float*)d_in[10];
    const float* bout = (const float*)d_in[11];
    float* out = (float*)d_out;

    void* p;
    unsigned *pxs, *pxt, *pma, *pmb, *pxt0, *pxs0, *pxs1;
    __nv_bfloat16 *wbh, *wbl;
    cudaGetSymbolAddress(&p, g_pxs);  pxs = (unsigned*)p;
    cudaGetSymbolAddress(&p, g_pxt);  pxt = (unsigned*)p;
    cudaGetSymbolAddress(&p, g_pma);  pma = (unsigned*)p;
    cudaGetSymbolAddress(&p, g_pmb);  pmb = (unsigned*)p;
    cudaGetSymbolAddress(&p, g_pxt0); pxt0 = (unsigned*)p;
    cudaGetSymbolAddress(&p, g_pxs0); pxs0 = (unsigned*)p;
    cudaGetSymbolAddress(&p, g_pxs1); pxs1 = (unsigned*)p;
    cudaGetSymbolAddress(&p, g_wbh);  wbh = (__nv_bfloat16*)p;
    cudaGetSymbolAddress(&p, g_wbl);  wbl = (__nv_bfloat16*)p;
    int *off_a, *off_b, *csr_a, *csr_b;
    cudaGetSymbolAddress(&p, g_off_a); off_a = (int*)p;
    cudaGetSymbolAddress(&p, g_off_b); off_b = (int*)p;
    cudaGetSymbolAddress(&p, g_csr_a); csr_a = (int*)p;
    cudaGetSymbolAddress(&p, g_csr_b); csr_b = (int*)p;

    cudaFuncSetAttribute(gemm_mma, cudaFuncAttributeMaxDynamicSharedMemorySize, SMEM_GEMM);

    const int* src_st = ei_st;
    const int* dst_st = ei_st + EE;
    const int* src_ts = ei_ts;
    const int* dst_ts = ei_ts + EE;

    // dropout keys: fold_in(key(42)=(0,42), d); d=0 -> xs0, d=1 -> xt0, d=2 -> xs1
    unsigned dkeys[3][2];
    for (int d = 0; d < 3; d++)
        tf2x32(0u, 42u, 0u, (unsigned)d, dkeys[d][0], dkeys[d][1]);

    // weight prep + input conversion + CSR build
    wprep_kernel<<<dim3(256, 8), 256>>>(Wl_st, Wr_st, Wl_ts, Wr_ts);
    conv_kernel<<<dim3(12500, 2), 256>>>(x_source, x_target);
    zero_kernel<<<(NN + 255) / 256, 256>>>();
    count_kernel<<<(EE + 255) / 256, 256>>>(dst_st, dst_ts);
    scan_pre<<<dim3(49, 2), 256>>>();
    scan_mid<<<dim3(1, 2), 64>>>();
    scan_add<<<dim3(49, 2), 256>>>();
    fill_kernel<<<(EE + 255) / 256, 256>>>(src_st, dst_st, src_ts, dst_ts);

    const int M64K = 65536;
    dim3 gGrid(2, NBLKY);

    // ---- layer 0 ----
    segmean_kernel<<<NN, 64>>>(pxs, off_a, csr_a, pma);   // m_t
    segmean_kernel<<<NN, 64>>>(pxt, off_b, csr_b, pmb);   // m_s
    gemm_mma<<<gGrid, 256, SMEM_GEMM>>>(pma, pxt, wbh + 0 * M64K, wbl + 0 * M64K,
                                        wbh + 1 * M64K, wbl + 1 * M64K, b_st, pxt0, NN,
                                        dkeys[1][0], dkeys[1][1]);
    gemm_mma<<<gGrid, 256, SMEM_GEMM>>>(pmb, pxs, wbh + 2 * M64K, wbl + 2 * M64K,
                                        wbh + 3 * M64K, wbl + 3 * M64K, b_ts, pxs0, NN,
                                        dkeys[0][0], dkeys[0][1]);

    // ---- layer 1 (only the source branch feeds the output; target branch is dead) ----
    segmean_kernel<<<NN, 64>>>(pxt0, off_b, csr_b, pma);  // m_s (layer 1)
    gemm_mma<<<gGrid, 256, SMEM_GEMM>>>(pma, pxs0, wbh + 6 * M64K, wbl + 6 * M64K,
                                        wbh + 7 * M64K, wbl + 7 * M64K, b_ts + 256, pxs1, NN,
                                        dkeys[2][0], dkeys[2][1]);

    // ---- output projection ----
    out_kernel<<<(NN + 15) / 16, 256>>>(pxs1, Wout, bout, out, NN);
}